// round 2
// baseline (speedup 1.0000x reference)
#include <cuda_runtime.h>
#include <cuda_fp16.h>

#define BATCH 4
#define N 4096
#define N2 (N / 2)
#define RN (BATCH * N)          // 16384 rows / batched columns
#define EPS 1e-6f
#define NITER 20

#define RPS 16                  // rows per strip (smem-resident)
#define SPB 2                   // strips per block
#define BPB (N / (RPS * SPB))   // 128 blocks per batch
#define GRID_FUSED (BATCH * BPB)// 512
#define FUSED_SMEM (RPS * N * 2)// 131072 bytes of fp16

// Scratch (device globals: allowed; no cudaMalloc)
__device__ __half g_E[(size_t)BATCH * N * N];    // 128 MB: exp(x - rowmax) fp16
__device__ float  g_r[RN];
__device__ float  g_c[RN];
__device__ float  g_rowmax[RN];
__device__ float  g_vpart[(size_t)GRID_FUSED * N]; // 8 MB col partials

__device__ __forceinline__ float warpSum(float v) {
    #pragma unroll
    for (int o = 16; o > 0; o >>= 1) v += __shfl_xor_sync(0xffffffffu, v, o);
    return v;
}
__device__ __forceinline__ float warpMax(float v) {
    #pragma unroll
    for (int o = 16; o > 0; o >>= 1) v = fmaxf(v, __shfl_xor_sync(0xffffffffu, v, o));
    return v;
}

// ---------------------------------------------------------------------------
// prep: per-row max, E = exp(x - max) in fp16, init r = c = 1
// ---------------------------------------------------------------------------
__global__ __launch_bounds__(256) void prep_kernel(const float* __restrict__ logits) {
    const int row = blockIdx.x;
    const int t   = threadIdx.x;
    const float4* src = (const float4*)(logits + (size_t)row * N);

    float4 vals[4];
    #pragma unroll
    for (int k = 0; k < 4; ++k) vals[k] = src[t + k * 256];

    float m = -__int_as_float(0x7f800000);
    #pragma unroll
    for (int k = 0; k < 4; ++k)
        m = fmaxf(m, fmaxf(fmaxf(vals[k].x, vals[k].y), fmaxf(vals[k].z, vals[k].w)));

    __shared__ float sh[32];
    __shared__ float s_max;
    float wm = warpMax(m);
    int lane = t & 31, w = t >> 5;
    if (lane == 0) sh[w] = wm;
    __syncthreads();
    if (w == 0) {
        float v = (lane < 8) ? sh[lane] : -__int_as_float(0x7f800000);
        v = warpMax(v);
        if (lane == 0) s_max = v;
    }
    __syncthreads();
    const float mx = s_max;

    __half2* dst = (__half2*)(g_E + (size_t)row * N);
    #pragma unroll
    for (int k = 0; k < 4; ++k) {
        const float4 v = vals[k];
        const int i4 = t + k * 256;
        dst[2 * i4 + 0] = __floats2half2_rn(__expf(v.x - mx), __expf(v.y - mx));
        dst[2 * i4 + 1] = __floats2half2_rn(__expf(v.z - mx), __expf(v.w - mx));
    }
    if (t == 0) {
        g_rowmax[row] = mx;
        g_r[row] = 1.0f;
        g_c[row] = 1.0f;
    }
}

// ---------------------------------------------------------------------------
// fused per-iteration kernel:
//   for each 16-row strip (2 strips per block):
//     phase A: stream E strip HBM->smem, simultaneously u_i = sum_j E_ij c_j
//              (warp w owns row w); update r_i in-place
//     phase B: column partials from smem: vacc_j += sum_i E_ij * r_i_new
//   write one column-partial vector per block (deterministic slots)
// ---------------------------------------------------------------------------
__global__ __launch_bounds__(512) void fused_kernel() {
    extern __shared__ __half2 sE2[];       // RPS x N2 half2 (128 KB)
    __shared__ float r_s[RPS];

    const int bid  = blockIdx.x;
    const int b    = bid >> 7;             // batch
    const int blk  = bid & (BPB - 1);
    const int t    = threadIdx.x;
    const int w    = t >> 5, lane = t & 31;

    const float2*  c2 = (const float2*)(g_c + b * N);
    const __half2* E2 = (const __half2*)g_E + (size_t)b * N * N2;

    float2 vacc[4] = {{0.f,0.f},{0.f,0.f},{0.f,0.f},{0.f,0.f}};

    #pragma unroll
    for (int s = 0; s < SPB; ++s) {
        const int lrow0 = blk * (RPS * SPB) + s * RPS;
        const int grow  = b * N + lrow0 + w;         // global row for warp w

        // phase A: load strip + row dot with c
        float acc = 0.0f;
        const __half2* erow = E2 + (size_t)(lrow0 + w) * N2;
        #pragma unroll 8
        for (int k = 0; k < N2 / 32; ++k) {
            const int j2 = k * 32 + lane;
            const __half2 e = erow[j2];
            sE2[w * N2 + j2] = e;
            const float2 ef = __half22float2(e);
            const float2 cf = c2[j2];
            acc = fmaf(ef.x, cf.x, acc);
            acc = fmaf(ef.y, cf.y, acc);
        }
        acc = warpSum(acc);
        if (lane == 0) {
            const float r  = g_r[grow];
            const float rn = r / fmaf(r, acc, EPS);
            g_r[grow] = rn;
            r_s[w]    = rn;
        }
        __syncthreads();

        // phase B: column partials from smem
        #pragma unroll
        for (int q = 0; q < 4; ++q) {
            const int j2 = q * 512 + t;
            float2 a = vacc[q];
            #pragma unroll
            for (int i = 0; i < RPS; ++i) {
                const float ri = r_s[i];
                const float2 ef = __half22float2(sE2[i * N2 + j2]);
                a.x = fmaf(ef.x, ri, a.x);
                a.y = fmaf(ef.y, ri, a.y);
            }
            vacc[q] = a;
        }
        __syncthreads();
    }

    float2* vp = (float2*)g_vpart + (size_t)bid * N2;
    #pragma unroll
    for (int q = 0; q < 4; ++q) vp[q * 512 + t] = vacc[q];
}

// ---------------------------------------------------------------------------
// finalize: v_j = sum over BPB block partials (fixed order); update c_j
// ---------------------------------------------------------------------------
__global__ __launch_bounds__(256) void col_finalize() {
    const int idx = blockIdx.x * 256 + threadIdx.x;   // 0..RN-1 = (b, j)
    const int b   = idx >> 12;
    const int j   = idx & (N - 1);
    const float* vp = g_vpart + (size_t)(b * BPB) * N + j;
    float v = 0.0f;
    #pragma unroll 16
    for (int s = 0; s < BPB; ++s) v += vp[(size_t)s * N];
    const float c = g_c[idx];
    g_c[idx] = c / fmaf(c, v, EPS);
}

// ---------------------------------------------------------------------------
// output: out_ij = exp(x_ij - rowmax_i) * r_i * c_j (fp32 path)
// ---------------------------------------------------------------------------
__global__ __launch_bounds__(256) void out_kernel(const float* __restrict__ logits,
                                                  float* __restrict__ out) {
    const size_t g  = (size_t)blockIdx.x * 256 + threadIdx.x;  // float4 index
    const size_t e0 = g * 4;
    const int row = (int)(e0 >> 12);
    const int b   = row >> 12;
    const int j   = (int)(e0 & (N - 1));

    const float mx = g_rowmax[row];
    const float r  = g_r[row];
    const float4 x = ((const float4*)logits)[g];
    const float4 c = *(const float4*)(g_c + b * N + j);

    float4 o;
    o.x = __expf(x.x - mx) * r * c.x;
    o.y = __expf(x.y - mx) * r * c.y;
    o.z = __expf(x.z - mx) * r * c.z;
    o.w = __expf(x.w - mx) * r * c.w;
    ((float4*)out)[g] = o;
}

extern "C" void kernel_launch(void* const* d_in, const int* in_sizes, int n_in,
                              void* d_out, int out_size) {
    const float* logits = (const float*)d_in[0];
    float* out = (float*)d_out;

    // >48KB dynamic smem needs opt-in; harmless if it no-ops during capture
    // (already applied on the correctness call).
    (void)cudaFuncSetAttribute(fused_kernel,
                               cudaFuncAttributeMaxDynamicSharedMemorySize,
                               FUSED_SMEM);

    prep_kernel<<<RN, 256>>>(logits);
    for (int it = 0; it < NITER; ++it) {
        fused_kernel<<<GRID_FUSED, 512, FUSED_SMEM>>>();
        col_finalize<<<RN / 256, 256>>>();
    }
    const int out_blocks = (int)(((size_t)BATCH * N * N / 4) / 256);  // 65536
    out_kernel<<<out_blocks, 256>>>(logits, out);
}

// round 3
// speedup vs baseline: 1.8152x; 1.8152x over previous
#include <cuda_runtime.h>
#include <cuda_fp16.h>

#define BATCH 4
#define N 4096
#define N2 (N / 2)
#define RN (BATCH * N)
#define EPS 1e-6f
#define NITER 20

// Device-global scratch
__device__ __half g_E[(size_t)BATCH * N * N];   // 128 MB fp16 exp(x - rowmax)
__device__ float  g_r[RN];
__device__ float  g_c[RN];
__device__ float  g_rowmax[RN];

__device__ __forceinline__ float warpSum(float v) {
    #pragma unroll
    for (int o = 16; o > 0; o >>= 1) v += __shfl_xor_sync(0xffffffffu, v, o);
    return v;
}
__device__ __forceinline__ float warpMax(float v) {
    #pragma unroll
    for (int o = 16; o > 0; o >>= 1) v = fmaxf(v, __shfl_xor_sync(0xffffffffu, v, o));
    return v;
}

// ---------------------------------------------------------------------------
// prep for one batch-pair: rowmax, E=fp16 exp, AND fold first row step:
//   u_i = sum_j E_ij (c=1), r_i = 1/(u_i+eps); c_j = 1
// one 256-thread block per row, 8192 blocks per pair
// ---------------------------------------------------------------------------
__global__ __launch_bounds__(256) void prep_pair(const float* __restrict__ logits,
                                                 int b0) {
    const int row = b0 * N + blockIdx.x;
    const int t   = threadIdx.x;
    const float4* src = (const float4*)(logits + (size_t)row * N);

    float4 vals[4];
    #pragma unroll
    for (int k = 0; k < 4; ++k) vals[k] = src[t + k * 256];

    float m = -__int_as_float(0x7f800000);
    #pragma unroll
    for (int k = 0; k < 4; ++k)
        m = fmaxf(m, fmaxf(fmaxf(vals[k].x, vals[k].y), fmaxf(vals[k].z, vals[k].w)));

    __shared__ float sh[32];
    __shared__ float s_bc;
    const int lane = t & 31, w = t >> 5;
    float wm = warpMax(m);
    if (lane == 0) sh[w] = wm;
    __syncthreads();
    if (w == 0) {
        float v = (lane < 8) ? sh[lane] : -__int_as_float(0x7f800000);
        v = warpMax(v);
        if (lane == 0) s_bc = v;
    }
    __syncthreads();
    const float mx = s_bc;
    __syncthreads();

    // write E (fp16) and accumulate row sum of the ROUNDED values
    __half2* dst = (__half2*)(g_E + (size_t)row * N);
    float sum = 0.0f;
    #pragma unroll
    for (int k = 0; k < 4; ++k) {
        const float4 v = vals[k];
        const int i4 = t + k * 256;
        const __half2 h0 = __floats2half2_rn(__expf(v.x - mx), __expf(v.y - mx));
        const __half2 h1 = __floats2half2_rn(__expf(v.z - mx), __expf(v.w - mx));
        dst[2 * i4 + 0] = h0;
        dst[2 * i4 + 1] = h1;
        const float2 f0 = __half22float2(h0), f1 = __half22float2(h1);
        sum += (f0.x + f0.y) + (f1.x + f1.y);
    }
    float ws = warpSum(sum);
    if (lane == 0) sh[w] = ws;
    __syncthreads();
    if (t == 0) {
        float u = 0.0f;
        #pragma unroll
        for (int i = 0; i < 8; ++i) u += sh[i];
        g_rowmax[row] = mx;
        g_r[row] = 1.0f / (u + EPS);   // first row step folded (r was 1)
        g_c[row] = 1.0f;
    }
}

// ---------------------------------------------------------------------------
// row pass (pair): u_i = sum_j E_ij c_j ; r_i <- r_i/(r_i u_i + eps)
// one warp per row; 512-thread blocks, 512 blocks per pair (L2-resident E)
// ---------------------------------------------------------------------------
__global__ __launch_bounds__(512) void row_pair(int b0) {
    const int t    = threadIdx.x;
    const int lane = t & 31;
    const int row  = b0 * N + blockIdx.x * 16 + (t >> 5);
    const int b    = row >> 12;

    const float4* er = (const float4*)(g_E + (size_t)row * N);  // 512 float4/row
    const float4* cb = (const float4*)(g_c + b * N);

    float acc = 0.0f;
    #pragma unroll 4
    for (int k = 0; k < 16; ++k) {
        const int idx = k * 32 + lane;
        const float4 ev = er[idx];
        const __half2 h0 = *(const __half2*)&ev.x;
        const __half2 h1 = *(const __half2*)&ev.y;
        const __half2 h2 = *(const __half2*)&ev.z;
        const __half2 h3 = *(const __half2*)&ev.w;
        const float4 c0 = cb[idx * 2];
        const float4 c1 = cb[idx * 2 + 1];
        const float2 f0 = __half22float2(h0), f1 = __half22float2(h1);
        const float2 f2 = __half22float2(h2), f3 = __half22float2(h3);
        acc = fmaf(f0.x, c0.x, acc); acc = fmaf(f0.y, c0.y, acc);
        acc = fmaf(f1.x, c0.z, acc); acc = fmaf(f1.y, c0.w, acc);
        acc = fmaf(f2.x, c1.x, acc); acc = fmaf(f2.y, c1.y, acc);
        acc = fmaf(f3.x, c1.z, acc); acc = fmaf(f3.y, c1.w, acc);
    }
    acc = warpSum(acc);
    if (lane == 0) {
        const float r = g_r[row];
        g_r[row] = r / fmaf(r, acc, EPS);
    }
}

// ---------------------------------------------------------------------------
// col pass (pair): block owns 16 full columns of one batch; no partials.
//   v_j = sum_i E_ij r_i ; c_j <- c_j/(c_j v_j + eps)
// 256 threads: thread = (uint2-col u2i of 4) x (row-chunk of 64)
// grid = 2 batches * 256 tiles = 512 blocks per pair
// ---------------------------------------------------------------------------
__global__ __launch_bounds__(256) void col_pair(int b0) {
    const int bb   = blockIdx.x >> 8;          // batch within pair
    const int b    = b0 + bb;
    const int tile = blockIdx.x & 255;         // 256 tiles of 16 cols
    const int t    = threadIdx.x;
    const int u2i  = t & 3;                    // uint2 (4 halfs) within 16 cols
    const int ch   = t >> 2;                   // 64 chunks of 64 rows

    const uint2* Eu = (const uint2*)(g_E + (size_t)b * N * N);  // 1024 uint2/row
    const float* rr = g_r + b * N;
    const int    cu = tile * 4 + u2i;

    float4 a = make_float4(0.f, 0.f, 0.f, 0.f);
    const int i0 = ch * 64;
    #pragma unroll 8
    for (int i = i0; i < i0 + 64; ++i) {
        const uint2 e = Eu[(size_t)i * (N / 4) + cu];
        const float ri = rr[i];
        const float2 f0 = __half22float2(*(const __half2*)&e.x);
        const float2 f1 = __half22float2(*(const __half2*)&e.y);
        a.x = fmaf(f0.x, ri, a.x);
        a.y = fmaf(f0.y, ri, a.y);
        a.z = fmaf(f1.x, ri, a.z);
        a.w = fmaf(f1.y, ri, a.w);
    }
    __shared__ float4 sv[256];
    sv[t] = a;
    __syncthreads();

    if (t < 16) {
        const int u2 = t >> 2, comp = t & 3;
        float v = 0.0f;
        #pragma unroll
        for (int c = 0; c < 64; ++c)
            v += ((const float*)&sv[c * 4 + u2])[comp];   // fixed order
        const int cj = b * N + tile * 16 + t;
        const float cc = g_c[cj];
        g_c[cj] = cc / fmaf(cc, v, EPS);
    }
}

// ---------------------------------------------------------------------------
// output (pair): out_ij = exp(x_ij - rowmax_i) * r_i * c_j  (fp32 path)
// ---------------------------------------------------------------------------
__global__ __launch_bounds__(256) void out_pair(const float* __restrict__ logits,
                                                float* __restrict__ out, int b0) {
    const size_t g  = (size_t)b0 * N * (N / 4) + (size_t)blockIdx.x * 256 + threadIdx.x;
    const size_t e0 = g * 4;
    const int row = (int)(e0 >> 12);
    const int b   = row >> 12;
    const int j   = (int)(e0 & (N - 1));

    const float mx = g_rowmax[row];
    const float r  = g_r[row];
    const float4 x = ((const float4*)logits)[g];
    const float4 c = *(const float4*)(g_c + b * N + j);

    float4 o;
    o.x = __expf(x.x - mx) * r * c.x;
    o.y = __expf(x.y - mx) * r * c.y;
    o.z = __expf(x.z - mx) * r * c.z;
    o.w = __expf(x.w - mx) * r * c.w;
    ((float4*)out)[g] = o;
}

extern "C" void kernel_launch(void* const* d_in, const int* in_sizes, int n_in,
                              void* d_out, int out_size) {
    const float* logits = (const float*)d_in[0];
    float* out = (float*)d_out;

    for (int bp = 0; bp < 2; ++bp) {
        const int b0 = bp * 2;
        prep_pair<<<2 * N, 256>>>(logits, b0);      // includes first row step
        col_pair<<<512, 256>>>(b0);                 // iteration 1 col step
        for (int it = 1; it < NITER; ++it) {
            row_pair<<<512, 512>>>(b0);
            col_pair<<<512, 256>>>(b0);
        }
        out_pair<<<2 * N * (N / 4) / 256, 256>>>(logits, out, b0);
    }
}

// round 4
// speedup vs baseline: 1.8556x; 1.0223x over previous
#include <cuda_runtime.h>
#include <cuda_fp16.h>

#define BATCH 4
#define N 4096
#define RN (BATCH * N)
#define EPS 1e-6f
#define NITER 20

#define RPS 16                   // rows per strip
#define SPBATCH (N / RPS)        // 256 strips per batch
#define GRID_F (BATCH * SPBATCH) // 1024 fused blocks

// Device-global scratch
__device__ __half g_E[(size_t)BATCH * N * N];       // 128 MB fp16 exp(x-rowmax)
__device__ float  g_r[RN];
__device__ float  g_c[RN];
__device__ float  g_rowmax[RN];
__device__ float  g_vpart[(size_t)GRID_F * N];      // 16 MB col partials

__device__ __forceinline__ float warpSum(float v) {
    #pragma unroll
    for (int o = 16; o > 0; o >>= 1) v += __shfl_xor_sync(0xffffffffu, v, o);
    return v;
}
__device__ __forceinline__ float warpMax(float v) {
    #pragma unroll
    for (int o = 16; o > 0; o >>= 1) v = fmaxf(v, __shfl_xor_sync(0xffffffffu, v, o));
    return v;
}

// ---------------------------------------------------------------------------
// prep: rowmax, E = fp16 exp(x - max), fold FIRST row step (c=1):
//   r_i = 1/(rowsum + eps);  c_j = 1
// ---------------------------------------------------------------------------
__global__ __launch_bounds__(256) void prep_kernel(const float* __restrict__ logits) {
    const int row = blockIdx.x;
    const int t   = threadIdx.x;
    const float4* src = (const float4*)(logits + (size_t)row * N);

    float4 vals[4];
    #pragma unroll
    for (int k = 0; k < 4; ++k) vals[k] = src[t + k * 256];

    float m = -__int_as_float(0x7f800000);
    #pragma unroll
    for (int k = 0; k < 4; ++k)
        m = fmaxf(m, fmaxf(fmaxf(vals[k].x, vals[k].y), fmaxf(vals[k].z, vals[k].w)));

    __shared__ float sh[32];
    __shared__ float s_bc;
    const int lane = t & 31, w = t >> 5;
    float wm = warpMax(m);
    if (lane == 0) sh[w] = wm;
    __syncthreads();
    if (w == 0) {
        float v = (lane < 8) ? sh[lane] : -__int_as_float(0x7f800000);
        v = warpMax(v);
        if (lane == 0) s_bc = v;
    }
    __syncthreads();
    const float mx = s_bc;
    __syncthreads();

    __half2* dst = (__half2*)(g_E + (size_t)row * N);
    float sum = 0.0f;
    #pragma unroll
    for (int k = 0; k < 4; ++k) {
        const float4 v = vals[k];
        const int i4 = t + k * 256;
        const __half2 h0 = __floats2half2_rn(__expf(v.x - mx), __expf(v.y - mx));
        const __half2 h1 = __floats2half2_rn(__expf(v.z - mx), __expf(v.w - mx));
        dst[2 * i4 + 0] = h0;
        dst[2 * i4 + 1] = h1;
        const float2 f0 = __half22float2(h0), f1 = __half22float2(h1);
        sum += (f0.x + f0.y) + (f1.x + f1.y);
    }
    float ws = warpSum(sum);
    if (lane == 0) sh[w] = ws;
    __syncthreads();
    if (t == 0) {
        float u = 0.0f;
        #pragma unroll
        for (int i = 0; i < 8; ++i) u += sh[i];
        g_rowmax[row] = mx;
        g_r[row] = 1.0f / (u + EPS);
        g_c[row] = 1.0f;
    }
}

// ---------------------------------------------------------------------------
// fused iteration kernel over one 16-row strip:
//  phase A (if do_row): warp w streams row w coalesced, u = E_row . c,
//                       r <- r/(r*u+eps)  (exclusive row ownership)
//  phase B: col partials v_j += sum_i E_ij * r_i from the L2-hot strip,
//           thread owns 8 consecutive columns; one partial slot per block
// ---------------------------------------------------------------------------
__global__ __launch_bounds__(512) void fused_kernel(int do_row) {
    __shared__ float r_s[RPS];

    const int bid   = blockIdx.x;
    const int b     = bid >> 8;              // batch
    const int strip = bid & (SPBATCH - 1);
    const int t     = threadIdx.x;
    const int w     = t >> 5, lane = t & 31;
    const int row0  = strip * RPS;           // within batch

    const uint4*  Eb = (const uint4*)(g_E + (size_t)b * N * N);  // 512 uint4/row
    const float4* cb = (const float4*)(g_c + b * N);

    if (do_row) {
        const int row  = row0 + w;
        const int grow = b * N + row;
        const uint4* er = Eb + (size_t)row * 512;
        float acc = 0.0f;
        #pragma unroll 4
        for (int k = 0; k < 16; ++k) {
            const int idx = k * 32 + lane;
            const uint4 e = er[idx];
            const float4 c0 = cb[2 * idx];
            const float4 c1 = cb[2 * idx + 1];
            const float2 f0 = __half22float2(*(const __half2*)&e.x);
            const float2 f1 = __half22float2(*(const __half2*)&e.y);
            const float2 f2 = __half22float2(*(const __half2*)&e.z);
            const float2 f3 = __half22float2(*(const __half2*)&e.w);
            acc = fmaf(f0.x, c0.x, acc); acc = fmaf(f0.y, c0.y, acc);
            acc = fmaf(f1.x, c0.z, acc); acc = fmaf(f1.y, c0.w, acc);
            acc = fmaf(f2.x, c1.x, acc); acc = fmaf(f2.y, c1.y, acc);
            acc = fmaf(f3.x, c1.z, acc); acc = fmaf(f3.y, c1.w, acc);
        }
        acc = warpSum(acc);
        if (lane == 0) {
            const float r  = g_r[grow];
            const float rn = r / fmaf(r, acc, EPS);
            g_r[grow] = rn;
            r_s[w]    = rn;
        }
    } else {
        if (t < RPS) r_s[t] = g_r[b * N + row0 + t];
    }
    __syncthreads();

    // phase B: thread t owns columns [8t, 8t+8)
    float a0 = 0.f, a1 = 0.f, a2 = 0.f, a3 = 0.f;
    float a4 = 0.f, a5 = 0.f, a6 = 0.f, a7 = 0.f;
    const uint4* Es = Eb + (size_t)row0 * 512 + t;
    #pragma unroll
    for (int i = 0; i < RPS; ++i) {
        const uint4 e = Es[(size_t)i * 512];
        const float ri = r_s[i];
        const float2 f0 = __half22float2(*(const __half2*)&e.x);
        const float2 f1 = __half22float2(*(const __half2*)&e.y);
        const float2 f2 = __half22float2(*(const __half2*)&e.z);
        const float2 f3 = __half22float2(*(const __half2*)&e.w);
        a0 = fmaf(f0.x, ri, a0); a1 = fmaf(f0.y, ri, a1);
        a2 = fmaf(f1.x, ri, a2); a3 = fmaf(f1.y, ri, a3);
        a4 = fmaf(f2.x, ri, a4); a5 = fmaf(f2.y, ri, a5);
        a6 = fmaf(f3.x, ri, a6); a7 = fmaf(f3.y, ri, a7);
    }
    float4* vp = (float4*)(g_vpart + (size_t)bid * N) + 2 * t;
    vp[0] = make_float4(a0, a1, a2, a3);
    vp[1] = make_float4(a4, a5, a6, a7);
}

// ---------------------------------------------------------------------------
// finalize: v_j = sum over 256 strip partials (fixed order); c update
// ---------------------------------------------------------------------------
__global__ __launch_bounds__(256) void col_finalize() {
    const int idx = blockIdx.x * 256 + threadIdx.x;   // (b, j)
    const int b   = idx >> 12;
    const int j   = idx & (N - 1);
    const float* vp = g_vpart + (size_t)(b * SPBATCH) * N + j;
    float v = 0.0f;
    #pragma unroll 8
    for (int s = 0; s < SPBATCH; ++s) v += vp[(size_t)s * N];
    const float c = g_c[idx];
    g_c[idx] = c / fmaf(c, v, EPS);
}

// ---------------------------------------------------------------------------
// output: out_ij = exp(x_ij - rowmax_i) * r_i * c_j (fp32 path)
// ---------------------------------------------------------------------------
__global__ __launch_bounds__(256) void out_kernel(const float* __restrict__ logits,
                                                  float* __restrict__ out) {
    const size_t g  = (size_t)blockIdx.x * 256 + threadIdx.x;  // float4 index
    const size_t e0 = g * 4;
    const int row = (int)(e0 >> 12);
    const int b   = row >> 12;
    const int j   = (int)(e0 & (N - 1));

    const float mx = g_rowmax[row];
    const float r  = g_r[row];
    const float4 x = ((const float4*)logits)[g];
    const float4 c = *(const float4*)(g_c + b * N + j);

    float4 o;
    o.x = __expf(x.x - mx) * r * c.x;
    o.y = __expf(x.y - mx) * r * c.y;
    o.z = __expf(x.z - mx) * r * c.z;
    o.w = __expf(x.w - mx) * r * c.w;
    ((float4*)out)[g] = o;
}

extern "C" void kernel_launch(void* const* d_in, const int* in_sizes, int n_in,
                              void* d_out, int out_size) {
    const float* logits = (const float*)d_in[0];
    float* out = (float*)d_out;

    prep_kernel<<<RN, 256>>>(logits);          // includes row step #1
    for (int it = 0; it < NITER; ++it) {
        fused_kernel<<<GRID_F, 512>>>(it > 0); // it=0: col only (row folded)
        col_finalize<<<RN / 256, 256>>>();
    }
    out_kernel<<<(int)(((size_t)BATCH * N * N / 4) / 256), 256>>>(logits, out);
}

// round 5
// speedup vs baseline: 2.0637x; 1.1121x over previous
#include <cuda_runtime.h>
#include <cuda_fp16.h>

#define BATCH 4
#define N 4096
#define RN (BATCH * N)
#define EPS 1e-6f
#define NITER 20

#define RPS 16                   // rows per strip
#define SPBATCH (N / RPS)        // 256 strips per batch
#define GRID_F (BATCH * SPBATCH) // 1024 fused blocks

// Device-global scratch
__device__ __half g_E[(size_t)BATCH * N * N];       // 128 MB fp16 exp(x-rowmax)
__device__ float  g_r[RN];
__device__ float  g_c[RN];
__device__ float  g_rowmax[RN];
__device__ float  g_vpart[(size_t)GRID_F * N];      // 16 MB col partials

__device__ __forceinline__ float warpSum(float v) {
    #pragma unroll
    for (int o = 16; o > 0; o >>= 1) v += __shfl_xor_sync(0xffffffffu, v, o);
    return v;
}
__device__ __forceinline__ float warpMax(float v) {
    #pragma unroll
    for (int o = 16; o > 0; o >>= 1) v = fmaxf(v, __shfl_xor_sync(0xffffffffu, v, o));
    return v;
}

// ---------------------------------------------------------------------------
// prep: rowmax, E = fp16 exp(x - max), fold FIRST row step (c=1):
//   r_i = 1/(rowsum + eps);  c_j = 1
// ---------------------------------------------------------------------------
__global__ __launch_bounds__(256) void prep_kernel(const float* __restrict__ logits) {
    const int row = blockIdx.x;
    const int t   = threadIdx.x;
    const float4* src = (const float4*)(logits + (size_t)row * N);

    float4 vals[4];
    #pragma unroll
    for (int k = 0; k < 4; ++k) vals[k] = src[t + k * 256];

    float m = -__int_as_float(0x7f800000);
    #pragma unroll
    for (int k = 0; k < 4; ++k)
        m = fmaxf(m, fmaxf(fmaxf(vals[k].x, vals[k].y), fmaxf(vals[k].z, vals[k].w)));

    __shared__ float sh[32];
    __shared__ float s_bc;
    const int lane = t & 31, w = t >> 5;
    float wm = warpMax(m);
    if (lane == 0) sh[w] = wm;
    __syncthreads();
    if (w == 0) {
        float v = (lane < 8) ? sh[lane] : -__int_as_float(0x7f800000);
        v = warpMax(v);
        if (lane == 0) s_bc = v;
    }
    __syncthreads();
    const float mx = s_bc;
    __syncthreads();

    __half2* dst = (__half2*)(g_E + (size_t)row * N);
    float sum = 0.0f;
    #pragma unroll
    for (int k = 0; k < 4; ++k) {
        const float4 v = vals[k];
        const int i4 = t + k * 256;
        const __half2 h0 = __floats2half2_rn(__expf(v.x - mx), __expf(v.y - mx));
        const __half2 h1 = __floats2half2_rn(__expf(v.z - mx), __expf(v.w - mx));
        dst[2 * i4 + 0] = h0;
        dst[2 * i4 + 1] = h1;
        const float2 f0 = __half22float2(h0), f1 = __half22float2(h1);
        sum += (f0.x + f0.y) + (f1.x + f1.y);
    }
    float ws = warpSum(sum);
    if (lane == 0) sh[w] = ws;
    __syncthreads();
    if (t == 0) {
        float u = 0.0f;
        #pragma unroll
        for (int i = 0; i < 8; ++i) u += sh[i];
        g_rowmax[row] = mx;
        g_r[row] = 1.0f / (u + EPS);
        g_c[row] = 1.0f;
    }
}

// ---------------------------------------------------------------------------
// fused iteration: ONE read of E per iteration.
// Thread t holds uint4 column-slice t of all 16 strip rows in registers.
//  phase A (if do_row): partial row dots (per-thread 8 cols x 16 rows),
//    warp-reduce each row, 16x16 smem reduce, update r for strip rows.
//  phase B: column sums from registers (thread-local!), write one partial.
// ---------------------------------------------------------------------------
__global__ __launch_bounds__(512) void fused_kernel(int do_row) {
    __shared__ float s_u[16 * 16];
    __shared__ float r_s[RPS];

    const int bid   = blockIdx.x;
    const int b     = bid >> 8;              // batch
    const int strip = bid & (SPBATCH - 1);
    const int t     = threadIdx.x;
    const int w     = t >> 5, lane = t & 31;
    const int row0  = strip * RPS;           // within batch

    const uint4* Eb = (const uint4*)(g_E + (size_t)b * N * N);  // 512 uint4/row
    const uint4* Es = Eb + (size_t)row0 * 512 + t;

    // my 8 c values (columns [8t, 8t+8))
    const float4* cb = (const float4*)(g_c + b * N);
    const float4 c0 = cb[2 * t];
    const float4 c1 = cb[2 * t + 1];

    // load entire strip slice into registers (16 independent LDG.128)
    uint4 e[RPS];
    #pragma unroll
    for (int i = 0; i < RPS; ++i) e[i] = Es[(size_t)i * 512];

    if (do_row) {
        float u_part[RPS];
        #pragma unroll
        for (int i = 0; i < RPS; ++i) {
            const float2 f0 = __half22float2(*(const __half2*)&e[i].x);
            const float2 f1 = __half22float2(*(const __half2*)&e[i].y);
            const float2 f2 = __half22float2(*(const __half2*)&e[i].z);
            const float2 f3 = __half22float2(*(const __half2*)&e[i].w);
            float a = 0.f;
            a = fmaf(f0.x, c0.x, a); a = fmaf(f0.y, c0.y, a);
            a = fmaf(f1.x, c0.z, a); a = fmaf(f1.y, c0.w, a);
            a = fmaf(f2.x, c1.x, a); a = fmaf(f2.y, c1.y, a);
            a = fmaf(f3.x, c1.z, a); a = fmaf(f3.y, c1.w, a);
            u_part[i] = a;
        }
        #pragma unroll
        for (int i = 0; i < RPS; ++i) u_part[i] = warpSum(u_part[i]);
        if (lane < RPS) s_u[w * RPS + lane] = u_part[lane];
        __syncthreads();
        if (w == 0 && lane < RPS) {
            float u = 0.f;
            #pragma unroll
            for (int w2 = 0; w2 < 16; ++w2) u += s_u[w2 * RPS + lane];
            const int grow = b * N + row0 + lane;
            const float r  = g_r[grow];
            const float rn = r / fmaf(r, u, EPS);
            g_r[grow] = rn;
            r_s[lane] = rn;
        }
    } else {
        if (t < RPS) r_s[t] = g_r[b * N + row0 + t];
    }
    __syncthreads();

    // phase B: thread-local column sums over the 16 register-held rows
    float a0 = 0.f, a1 = 0.f, a2 = 0.f, a3 = 0.f;
    float a4 = 0.f, a5 = 0.f, a6 = 0.f, a7 = 0.f;
    #pragma unroll
    for (int i = 0; i < RPS; ++i) {
        const float ri = r_s[i];
        const float2 f0 = __half22float2(*(const __half2*)&e[i].x);
        const float2 f1 = __half22float2(*(const __half2*)&e[i].y);
        const float2 f2 = __half22float2(*(const __half2*)&e[i].z);
        const float2 f3 = __half22float2(*(const __half2*)&e[i].w);
        a0 = fmaf(f0.x, ri, a0); a1 = fmaf(f0.y, ri, a1);
        a2 = fmaf(f1.x, ri, a2); a3 = fmaf(f1.y, ri, a3);
        a4 = fmaf(f2.x, ri, a4); a5 = fmaf(f2.y, ri, a5);
        a6 = fmaf(f3.x, ri, a6); a7 = fmaf(f3.y, ri, a7);
    }
    float4* vp = (float4*)(g_vpart + (size_t)bid * N) + 2 * t;
    vp[0] = make_float4(a0, a1, a2, a3);
    vp[1] = make_float4(a4, a5, a6, a7);
}

// ---------------------------------------------------------------------------
// finalize: v_j = sum over 256 strip partials (fixed order); c update
// ---------------------------------------------------------------------------
__global__ __launch_bounds__(256) void col_finalize() {
    const int idx = blockIdx.x * 256 + threadIdx.x;   // (b, j)
    const int b   = idx >> 12;
    const int j   = idx & (N - 1);
    const float* vp = g_vpart + (size_t)(b * SPBATCH) * N + j;
    float v = 0.0f;
    #pragma unroll 8
    for (int s = 0; s < SPBATCH; ++s) v += vp[(size_t)s * N];
    const float c = g_c[idx];
    g_c[idx] = c / fmaf(c, v, EPS);
}

// ---------------------------------------------------------------------------
// output: out_ij = exp(x_ij - rowmax_i) * r_i * c_j (fp32 path)
// ---------------------------------------------------------------------------
__global__ __launch_bounds__(256) void out_kernel(const float* __restrict__ logits,
                                                  float* __restrict__ out) {
    const size_t g  = (size_t)blockIdx.x * 256 + threadIdx.x;  // float4 index
    const size_t e0 = g * 4;
    const int row = (int)(e0 >> 12);
    const int b   = row >> 12;
    const int j   = (int)(e0 & (N - 1));

    const float mx = g_rowmax[row];
    const float r  = g_r[row];
    const float4 x = ((const float4*)logits)[g];
    const float4 c = *(const float4*)(g_c + b * N + j);

    float4 o;
    o.x = __expf(x.x - mx) * r * c.x;
    o.y = __expf(x.y - mx) * r * c.y;
    o.z = __expf(x.z - mx) * r * c.z;
    o.w = __expf(x.w - mx) * r * c.w;
    ((float4*)out)[g] = o;
}

extern "C" void kernel_launch(void* const* d_in, const int* in_sizes, int n_in,
                              void* d_out, int out_size) {
    const float* logits = (const float*)d_in[0];
    float* out = (float*)d_out;

    prep_kernel<<<RN, 256>>>(logits);          // includes row step #1
    for (int it = 0; it < NITER; ++it) {
        fused_kernel<<<GRID_F, 512>>>(it > 0); // it=0: col only (row folded)
        col_finalize<<<RN / 256, 256>>>();
    }
    out_kernel<<<(int)(((size_t)BATCH * N * N / 4) / 256), 256>>>(logits, out);
}

// round 6
// speedup vs baseline: 2.9432x; 1.4262x over previous
#include <cuda_runtime.h>
#include <cuda_fp16.h>

#define BATCH 4
#define N 4096
#define RN (BATCH * N)
#define EPS 1e-6f
#define NITER 20

#define RPG 8                    // rows per group (register-resident)
#define GROUPS 2                 // groups per block -> 16 rows per block
#define RPS (RPG * GROUPS)
#define SPBATCH (N / RPS)        // 256 strips per batch
#define GRID_F (BATCH * SPBATCH) // 1024 fused blocks

// Device-global scratch
__device__ __half g_E[(size_t)BATCH * N * N];       // 128 MB fp16 exp(x-rowmax)
__device__ float  g_r[RN];
__device__ float  g_c[RN];
__device__ float  g_rowmax[RN];
__device__ float  g_vpart[(size_t)GRID_F * N];      // 16 MB col partials

__device__ __forceinline__ float warpSum(float v) {
    #pragma unroll
    for (int o = 16; o > 0; o >>= 1) v += __shfl_xor_sync(0xffffffffu, v, o);
    return v;
}
__device__ __forceinline__ float warpMax(float v) {
    #pragma unroll
    for (int o = 16; o > 0; o >>= 1) v = fmaxf(v, __shfl_xor_sync(0xffffffffu, v, o));
    return v;
}

// ---------------------------------------------------------------------------
// prep: rowmax, E = fp16 exp(x - max), fold FIRST row step (c=1):
//   r_i = 1/(rowsum + eps);  c_j = 1
// ---------------------------------------------------------------------------
__global__ __launch_bounds__(256) void prep_kernel(const float* __restrict__ logits) {
    const int row = blockIdx.x;
    const int t   = threadIdx.x;
    const float4* src = (const float4*)(logits + (size_t)row * N);

    float4 vals[4];
    #pragma unroll
    for (int k = 0; k < 4; ++k) vals[k] = src[t + k * 256];

    float m = -__int_as_float(0x7f800000);
    #pragma unroll
    for (int k = 0; k < 4; ++k)
        m = fmaxf(m, fmaxf(fmaxf(vals[k].x, vals[k].y), fmaxf(vals[k].z, vals[k].w)));

    __shared__ float sh[32];
    __shared__ float s_bc;
    const int lane = t & 31, w = t >> 5;
    float wm = warpMax(m);
    if (lane == 0) sh[w] = wm;
    __syncthreads();
    if (w == 0) {
        float v = (lane < 8) ? sh[lane] : -__int_as_float(0x7f800000);
        v = warpMax(v);
        if (lane == 0) s_bc = v;
    }
    __syncthreads();
    const float mx = s_bc;
    __syncthreads();

    __half2* dst = (__half2*)(g_E + (size_t)row * N);
    float sum = 0.0f;
    #pragma unroll
    for (int k = 0; k < 4; ++k) {
        const float4 v = vals[k];
        const int i4 = t + k * 256;
        const __half2 h0 = __floats2half2_rn(__expf(v.x - mx), __expf(v.y - mx));
        const __half2 h1 = __floats2half2_rn(__expf(v.z - mx), __expf(v.w - mx));
        dst[2 * i4 + 0] = h0;
        dst[2 * i4 + 1] = h1;
        const float2 f0 = __half22float2(h0), f1 = __half22float2(h1);
        sum += (f0.x + f0.y) + (f1.x + f1.y);
    }
    float ws = warpSum(sum);
    if (lane == 0) sh[w] = ws;
    __syncthreads();
    if (t == 0) {
        float u = 0.0f;
        #pragma unroll
        for (int i = 0; i < 8; ++i) u += sh[i];
        g_rowmax[row] = mx;
        g_r[row] = 1.0f / (u + EPS);
        g_c[row] = 1.0f;
    }
}

// ---------------------------------------------------------------------------
// fused iteration: ONE read of E per iteration, 8-row register groups.
// Block owns 16 rows (2 groups of 8). Thread t owns uint4 column-slice t.
// Per group: phase A row dots -> update r; phase B thread-local col sums.
// ---------------------------------------------------------------------------
__global__ __launch_bounds__(512, 2) void fused_kernel(int do_row) {
    __shared__ float s_u[16 * RPG];
    __shared__ float r_s[RPG];

    const int bid   = blockIdx.x;
    const int b     = bid >> 8;              // batch
    const int strip = bid & (SPBATCH - 1);
    const int t     = threadIdx.x;
    const int w     = t >> 5, lane = t & 31;
    const int row0  = strip * RPS;           // within batch

    const uint4* Eb = (const uint4*)(g_E + (size_t)b * N * N);  // 512 uint4/row

    // my 8 c values (columns [8t, 8t+8))
    const float4* cb = (const float4*)(g_c + b * N);
    const float4 c0 = cb[2 * t];
    const float4 c1 = cb[2 * t + 1];

    float a0 = 0.f, a1 = 0.f, a2 = 0.f, a3 = 0.f;
    float a4 = 0.f, a5 = 0.f, a6 = 0.f, a7 = 0.f;

    #pragma unroll
    for (int grp = 0; grp < GROUPS; ++grp) {
        const int rowg = row0 + grp * RPG;
        const uint4* Es = Eb + (size_t)rowg * 512 + t;

        uint4 e[RPG];
        #pragma unroll
        for (int i = 0; i < RPG; ++i) e[i] = Es[(size_t)i * 512];

        if (do_row) {
            float u_part[RPG];
            #pragma unroll
            for (int i = 0; i < RPG; ++i) {
                const float2 f0 = __half22float2(*(const __half2*)&e[i].x);
                const float2 f1 = __half22float2(*(const __half2*)&e[i].y);
                const float2 f2 = __half22float2(*(const __half2*)&e[i].z);
                const float2 f3 = __half22float2(*(const __half2*)&e[i].w);
                float a = 0.f;
                a = fmaf(f0.x, c0.x, a); a = fmaf(f0.y, c0.y, a);
                a = fmaf(f1.x, c0.z, a); a = fmaf(f1.y, c0.w, a);
                a = fmaf(f2.x, c1.x, a); a = fmaf(f2.y, c1.y, a);
                a = fmaf(f3.x, c1.z, a); a = fmaf(f3.y, c1.w, a);
                u_part[i] = a;
            }
            #pragma unroll
            for (int i = 0; i < RPG; ++i) u_part[i] = warpSum(u_part[i]);
            if (lane < RPG) s_u[w * RPG + lane] = u_part[lane];
            __syncthreads();
            if (w == 0 && lane < RPG) {
                float u = 0.f;
                #pragma unroll
                for (int w2 = 0; w2 < 16; ++w2) u += s_u[w2 * RPG + lane];
                const int grow = b * N + rowg + lane;
                const float r  = g_r[grow];
                const float rn = r / fmaf(r, u, EPS);
                g_r[grow] = rn;
                r_s[lane] = rn;
            }
        } else {
            if (t < RPG) r_s[t] = g_r[b * N + rowg + t];
        }
        __syncthreads();

        // phase B: thread-local column sums over register-held rows
        #pragma unroll
        for (int i = 0; i < RPG; ++i) {
            const float ri = r_s[i];
            const float2 f0 = __half22float2(*(const __half2*)&e[i].x);
            const float2 f1 = __half22float2(*(const __half2*)&e[i].y);
            const float2 f2 = __half22float2(*(const __half2*)&e[i].z);
            const float2 f3 = __half22float2(*(const __half2*)&e[i].w);
            a0 = fmaf(f0.x, ri, a0); a1 = fmaf(f0.y, ri, a1);
            a2 = fmaf(f1.x, ri, a2); a3 = fmaf(f1.y, ri, a3);
            a4 = fmaf(f2.x, ri, a4); a5 = fmaf(f2.y, ri, a5);
            a6 = fmaf(f3.x, ri, a6); a7 = fmaf(f3.y, ri, a7);
        }
        __syncthreads();   // protect r_s before next group's phase A rewrites it
    }

    float4* vp = (float4*)(g_vpart + (size_t)bid * N) + 2 * t;
    vp[0] = make_float4(a0, a1, a2, a3);
    vp[1] = make_float4(a4, a5, a6, a7);
}

// ---------------------------------------------------------------------------
// finalize: 4 threads per column, each sums 64 strip-partials sequentially
// (fixed order), then fixed-order shfl combine -> deterministic. c update.
// ---------------------------------------------------------------------------
__global__ __launch_bounds__(256) void col_finalize() {
    const int tt  = threadIdx.x;
    const int col = blockIdx.x * 64 + (tt >> 2);   // global (b,j) column, 0..RN-1
    const int q   = tt & 3;
    const int b   = col >> 12;
    const int j   = col & (N - 1);

    const float* vp = g_vpart + (size_t)(b * SPBATCH + q * 64) * N + j;
    float v = 0.0f;
    #pragma unroll 8
    for (int s = 0; s < 64; ++s) v += vp[(size_t)s * N];

    // fixed-order combine across the 4 q-threads (same column)
    v += __shfl_down_sync(0xffffffffu, v, 1);
    v += __shfl_down_sync(0xffffffffu, v, 2);
    if (q == 0) {
        const float c = g_c[col];
        g_c[col] = c / fmaf(c, v, EPS);
    }
}

// ---------------------------------------------------------------------------
// output: out_ij = exp(x_ij - rowmax_i) * r_i * c_j (fp32 path)
// ---------------------------------------------------------------------------
__global__ __launch_bounds__(256) void out_kernel(const float* __restrict__ logits,
                                                  float* __restrict__ out) {
    const size_t g  = (size_t)blockIdx.x * 256 + threadIdx.x;  // float4 index
    const size_t e0 = g * 4;
    const int row = (int)(e0 >> 12);
    const int b   = row >> 12;
    const int j   = (int)(e0 & (N - 1));

    const float mx = g_rowmax[row];
    const float r  = g_r[row];
    const float4 x = ((const float4*)logits)[g];
    const float4 c = *(const float4*)(g_c + b * N + j);

    float4 o;
    o.x = __expf(x.x - mx) * r * c.x;
    o.y = __expf(x.y - mx) * r * c.y;
    o.z = __expf(x.z - mx) * r * c.z;
    o.w = __expf(x.w - mx) * r * c.w;
    ((float4*)out)[g] = o;
}

extern "C" void kernel_launch(void* const* d_in, const int* in_sizes, int n_in,
                              void* d_out, int out_size) {
    const float* logits = (const float*)d_in[0];
    float* out = (float*)d_out;

    prep_kernel<<<RN, 256>>>(logits);          // includes row step #1
    for (int it = 0; it < NITER; ++it) {
        fused_kernel<<<GRID_F, 512>>>(it > 0); // it=0: col only (row folded)
        col_finalize<<<RN / 64, 256>>>();
    }
    out_kernel<<<(int)(((size_t)BATCH * N * N / 4) / 256), 256>>>(logits, out);
}

// round 7
// speedup vs baseline: 2.9733x; 1.0102x over previous
#include <cuda_runtime.h>
#include <cuda_fp16.h>

#define BATCH 4
#define N 4096
#define RN (BATCH * N)
#define EPS 1e-6f
#define NITER 20

#define RPG 8                    // rows per group (register-resident)
#define GROUPS 2                 // groups per block -> 16 rows per block
#define RPS (RPG * GROUPS)
#define SPBATCH (N / RPS)        // 256 strips per batch
#define GRID_F (BATCH * SPBATCH) // 1024 fused blocks

typedef unsigned long long u64;

// Device-global scratch
__device__ __half g_E[(size_t)BATCH * N * N];       // 128 MB fp16 exp(x-rowmax)
__device__ float  g_r[RN];
__device__ float  g_c[RN];
__device__ float  g_rowmax[RN];
__device__ float  g_vpart[(size_t)GRID_F * N];      // 16 MB col partials

// ---- packed f32x2 helpers (Blackwell) ----
__device__ __forceinline__ u64 pack_f2(float x, float y) {
    u64 u; asm("mov.b64 %0, {%1, %2};" : "=l"(u) : "f"(x), "f"(y)); return u;
}
__device__ __forceinline__ float2 unpack_f2(u64 u) {
    float2 f; asm("mov.b64 {%0, %1}, %2;" : "=f"(f.x), "=f"(f.y) : "l"(u)); return f;
}
__device__ __forceinline__ u64 fma2(u64 a, u64 b, u64 c) {
    u64 d; asm("fma.rn.f32x2 %0, %1, %2, %3;" : "=l"(d) : "l"(a), "l"(b), "l"(c)); return d;
}
__device__ __forceinline__ u64 mul2(u64 a, u64 b) {
    u64 d; asm("mul.rn.f32x2 %0, %1, %2;" : "=l"(d) : "l"(a), "l"(b)); return d;
}
__device__ __forceinline__ u64 h2f2(__half2 h) {
    float2 f = __half22float2(h); return pack_f2(f.x, f.y);
}

__device__ __forceinline__ float warpSum(float v) {
    #pragma unroll
    for (int o = 16; o > 0; o >>= 1) v += __shfl_xor_sync(0xffffffffu, v, o);
    return v;
}
__device__ __forceinline__ float warpMax(float v) {
    #pragma unroll
    for (int o = 16; o > 0; o >>= 1) v = fmaxf(v, __shfl_xor_sync(0xffffffffu, v, o));
    return v;
}

// ---------------------------------------------------------------------------
// prep: rowmax, E = fp16 exp(x - max), fold FIRST row step (c=1):
//   r_i = 1/(rowsum + eps);  c_j = 1
// ---------------------------------------------------------------------------
__global__ __launch_bounds__(256) void prep_kernel(const float* __restrict__ logits) {
    const int row = blockIdx.x;
    const int t   = threadIdx.x;
    const float4* src = (const float4*)(logits + (size_t)row * N);

    float4 vals[4];
    #pragma unroll
    for (int k = 0; k < 4; ++k) vals[k] = src[t + k * 256];

    float m = -__int_as_float(0x7f800000);
    #pragma unroll
    for (int k = 0; k < 4; ++k)
        m = fmaxf(m, fmaxf(fmaxf(vals[k].x, vals[k].y), fmaxf(vals[k].z, vals[k].w)));

    __shared__ float sh[32];
    __shared__ float s_bc;
    const int lane = t & 31, w = t >> 5;
    float wm = warpMax(m);
    if (lane == 0) sh[w] = wm;
    __syncthreads();
    if (w == 0) {
        float v = (lane < 8) ? sh[lane] : -__int_as_float(0x7f800000);
        v = warpMax(v);
        if (lane == 0) s_bc = v;
    }
    __syncthreads();
    const float mx = s_bc;
    __syncthreads();

    __half2* dst = (__half2*)(g_E + (size_t)row * N);
    float sum = 0.0f;
    #pragma unroll
    for (int k = 0; k < 4; ++k) {
        const float4 v = vals[k];
        const int i4 = t + k * 256;
        const __half2 h0 = __floats2half2_rn(__expf(v.x - mx), __expf(v.y - mx));
        const __half2 h1 = __floats2half2_rn(__expf(v.z - mx), __expf(v.w - mx));
        dst[2 * i4 + 0] = h0;
        dst[2 * i4 + 1] = h1;
        const float2 f0 = __half22float2(h0), f1 = __half22float2(h1);
        sum += (f0.x + f0.y) + (f1.x + f1.y);
    }
    float ws = warpSum(sum);
    if (lane == 0) sh[w] = ws;
    __syncthreads();
    if (t == 0) {
        float u = 0.0f;
        #pragma unroll
        for (int i = 0; i < 8; ++i) u += sh[i];
        g_rowmax[row] = mx;
        g_r[row] = 1.0f / (u + EPS);
        g_c[row] = 1.0f;
    }
}

// ---------------------------------------------------------------------------
// fused iteration: ONE read of E, f32x2 packed math, folded warp reduction.
// Block owns 16 rows (2 groups of 8). Thread t owns uint4 column-slice t.
// ---------------------------------------------------------------------------
__global__ __launch_bounds__(512, 2) void fused_kernel(int do_row) {
    __shared__ float s_u[2][RPG * 16];   // [parity][row*16 + warp]
    __shared__ float r_s[2][RPG];

    const int bid   = blockIdx.x;
    const int b     = bid >> 8;              // batch
    const int strip = bid & (SPBATCH - 1);
    const int t     = threadIdx.x;
    const int w     = t >> 5, lane = t & 31;
    const int row0  = strip * RPS;           // within batch

    const uint4* Eb = (const uint4*)(g_E + (size_t)b * N * N);  // 512 uint4/row

    // my 8 c values (columns [8t, 8t+8)) packed as f32x2
    const float4* cb = (const float4*)(g_c + b * N);
    const float4 cA = cb[2 * t];
    const float4 cB = cb[2 * t + 1];
    const u64 c01 = pack_f2(cA.x, cA.y), c23 = pack_f2(cA.z, cA.w);
    const u64 c45 = pack_f2(cB.x, cB.y), c67 = pack_f2(cB.z, cB.w);

    u64 a01 = 0ull, a23 = 0ull, a45 = 0ull, a67 = 0ull;  // packed col accumulators

    #pragma unroll
    for (int grp = 0; grp < GROUPS; ++grp) {
        const int p    = grp & 1;
        const int rowg = row0 + grp * RPG;
        const uint4* Es = Eb + (size_t)rowg * 512 + t;

        uint4 e[RPG];
        #pragma unroll
        for (int i = 0; i < RPG; ++i) e[i] = Es[(size_t)i * 512];

        if (do_row) {
            float v[RPG];
            #pragma unroll
            for (int i = 0; i < RPG; ++i) {
                const __half2* ep = (const __half2*)&e[i];
                const u64 f0 = h2f2(ep[0]), f1 = h2f2(ep[1]);
                const u64 f2 = h2f2(ep[2]), f3 = h2f2(ep[3]);
                u64 pa = mul2(f0, c01);
                u64 pb = mul2(f1, c23);
                pa = fma2(f2, c45, pa);
                pb = fma2(f3, c67, pb);
                const float2 fa = unpack_f2(pa), fb = unpack_f2(pb);
                v[i] = (fa.x + fa.y) + (fb.x + fb.y);
            }
            // folded multi-value warp reduction: 16 shfl + 16 add
            #pragma unroll
            for (int i = 0; i < 4; ++i) {
                const float ta = __shfl_xor_sync(0xffffffffu, v[i], 16);
                const float tb = __shfl_xor_sync(0xffffffffu, v[i + 4], 16);
                v[i] = (lane < 16) ? (v[i] + ta) : (v[i + 4] + tb);
            }
            #pragma unroll
            for (int i = 0; i < 2; ++i) {
                const float ta = __shfl_xor_sync(0xffffffffu, v[i], 8);
                const float tb = __shfl_xor_sync(0xffffffffu, v[i + 2], 8);
                v[i] = ((lane & 8) == 0) ? (v[i] + ta) : (v[i + 2] + tb);
            }
            {
                const float ta = __shfl_xor_sync(0xffffffffu, v[0], 4);
                const float tb = __shfl_xor_sync(0xffffffffu, v[1], 4);
                v[0] = ((lane & 4) == 0) ? (v[0] + ta) : (v[1] + tb);
            }
            v[0] += __shfl_xor_sync(0xffffffffu, v[0], 2);
            v[0] += __shfl_xor_sync(0xffffffffu, v[0], 1);
            // lane (4k) holds full warp sum of row k (k = lane>>2)
            if ((lane & 3) == 0) s_u[p][(lane >> 2) * 16 + w] = v[0];
            __syncthreads();
            if (t < RPG) {
                float u = 0.f;
                #pragma unroll
                for (int w2 = 0; w2 < 16; ++w2) u += s_u[p][t * 16 + w2];
                const int grow = b * N + rowg + t;
                const float r  = g_r[grow];
                const float rn = r / fmaf(r, u, EPS);
                g_r[grow] = rn;
                r_s[p][t] = rn;
            }
        } else {
            if (t < RPG) r_s[p][t] = g_r[b * N + rowg + t];
        }
        __syncthreads();

        // phase B: packed column accumulation over register-held rows
        #pragma unroll
        for (int i = 0; i < RPG; ++i) {
            const float ri = r_s[p][i];
            const u64 ri2 = pack_f2(ri, ri);
            const __half2* ep = (const __half2*)&e[i];
            a01 = fma2(h2f2(ep[0]), ri2, a01);
            a23 = fma2(h2f2(ep[1]), ri2, a23);
            a45 = fma2(h2f2(ep[2]), ri2, a45);
            a67 = fma2(h2f2(ep[3]), ri2, a67);
        }
        // no trailing barrier: next group uses the other parity buffers,
        // and its __syncthreads (above) orders r_s reads before overwrite
    }

    const float2 f01 = unpack_f2(a01), f23 = unpack_f2(a23);
    const float2 f45 = unpack_f2(a45), f67 = unpack_f2(a67);
    float4* vp = (float4*)(g_vpart + (size_t)bid * N) + 2 * t;
    vp[0] = make_float4(f01.x, f01.y, f23.x, f23.y);
    vp[1] = make_float4(f45.x, f45.y, f67.x, f67.y);
}

// ---------------------------------------------------------------------------
// finalize: 4 threads per column, each sums 64 strip-partials sequentially
// (fixed order), then fixed-order shfl combine -> deterministic. c update.
// ---------------------------------------------------------------------------
__global__ __launch_bounds__(256) void col_finalize() {
    const int tt  = threadIdx.x;
    const int col = blockIdx.x * 64 + (tt >> 2);   // global (b,j) column
    const int q   = tt & 3;
    const int b   = col >> 12;
    const int j   = col & (N - 1);

    const float* vp = g_vpart + (size_t)(b * SPBATCH + q * 64) * N + j;
    float v = 0.0f;
    #pragma unroll 8
    for (int s = 0; s < 64; ++s) v += vp[(size_t)s * N];

    v += __shfl_down_sync(0xffffffffu, v, 1);
    v += __shfl_down_sync(0xffffffffu, v, 2);
    if (q == 0) {
        const float c = g_c[col];
        g_c[col] = c / fmaf(c, v, EPS);
    }
}

// ---------------------------------------------------------------------------
// output: out_ij = exp(x_ij - rowmax_i) * r_i * c_j (fp32 path)
// ---------------------------------------------------------------------------
__global__ __launch_bounds__(256) void out_kernel(const float* __restrict__ logits,
                                                  float* __restrict__ out) {
    const size_t g  = (size_t)blockIdx.x * 256 + threadIdx.x;  // float4 index
    const size_t e0 = g * 4;
    const int row = (int)(e0 >> 12);
    const int b   = row >> 12;
    const int j   = (int)(e0 & (N - 1));

    const float mx = g_rowmax[row];
    const float r  = g_r[row];
    const float4 x = ((const float4*)logits)[g];
    const float4 c = *(const float4*)(g_c + b * N + j);

    float4 o;
    o.x = __expf(x.x - mx) * r * c.x;
    o.y = __expf(x.y - mx) * r * c.y;
    o.z = __expf(x.z - mx) * r * c.z;
    o.w = __expf(x.w - mx) * r * c.w;
    ((float4*)out)[g] = o;
}

extern "C" void kernel_launch(void* const* d_in, const int* in_sizes, int n_in,
                              void* d_out, int out_size) {
    const float* logits = (const float*)d_in[0];
    float* out = (float*)d_out;

    prep_kernel<<<RN, 256>>>(logits);          // includes row step #1
    for (int it = 0; it < NITER; ++it) {
        fused_kernel<<<GRID_F, 512>>>(it > 0); // it=0: col only (row folded)
        col_finalize<<<RN / 64, 256>>>();
    }
    out_kernel<<<(int)(((size_t)BATCH * N * N / 4) / 256), 256>>>(logits, out);
}